// round 11
// baseline (speedup 1.0000x reference)
#include <cuda_runtime.h>

#define N 256
#define NMASK 255
#define PLANE (N * N)            // 65536
#define VOL   (N * N * N)        // 16777216
#define FULLM 0xffffffffu

struct V8 { float f0, f1, f2, f3, f4, f5, f6, f7; };

__device__ __forceinline__ V8 ldg_v8(const float* p) {
    V8 r;
    asm("ld.global.v8.f32 {%0,%1,%2,%3,%4,%5,%6,%7}, [%8];"
        : "=f"(r.f0), "=f"(r.f1), "=f"(r.f2), "=f"(r.f3),
          "=f"(r.f4), "=f"(r.f5), "=f"(r.f6), "=f"(r.f7)
        : "l"(p));
    return r;
}

__device__ __forceinline__ void stg_v8(float* p, const V8& v) {
    asm volatile("st.global.v8.f32 [%0], {%1,%2,%3,%4,%5,%6,%7,%8};"
        :: "l"(p),
           "f"(v.f0), "f"(v.f1), "f"(v.f2), "f"(v.f3),
           "f"(v.f4), "f"(v.f5), "f"(v.f6), "f"(v.f7)
        : "memory");
}

__device__ __forceinline__ V8 diff_scale(const V8& a, const V8& b) {
    V8 r;
    r.f0 = (a.f0 - b.f0) * 0.5f;  r.f1 = (a.f1 - b.f1) * 0.5f;
    r.f2 = (a.f2 - b.f2) * 0.5f;  r.f3 = (a.f3 - b.f3) * 0.5f;
    r.f4 = (a.f4 - b.f4) * 0.5f;  r.f5 = (a.f5 - b.f5) * 0.5f;
    r.f6 = (a.f6 - b.f6) * 0.5f;  r.f7 = (a.f7 - b.f7) * 0.5f;
    return r;
}

// One warp owns one full z-row (32 lanes x 8 floats = 256).
// Block: 512 threads = 16 warps = 16 y-rows.
// Grid: b(4) * x(256) * ygroups(16) = 16384 blocks.
__global__ __launch_bounds__(512)
void fd_grad_kernel(const float* __restrict__ v, float* __restrict__ out) {
    const int t    = threadIdx.x;
    const int w    = t >> 5;            // warp = row slot 0..15
    const int lane = t & 31;

    const unsigned bid = blockIdx.x;
    const int yb = bid & 15;              // y-group of 16 rows
    const int x  = (bid >> 4) & NMASK;    // x plane
    const int b  = bid >> 12;             // batch

    const int y  = (yb << 4) | w;

    const long long bvol = (long long)b * VOL;
    const float* __restrict__ basep = v + bvol + (long long)x * PLANE;
    const long long roff = (long long)y * N + lane * 8;

    // ---- loads (5 x 256-bit) ----
    const int yp = (y + 1) & NMASK;
    const int ym = (y - 1) & NMASK;
    const int xp = (x + 1) & NMASK;
    const int xm = (x - 1) & NMASK;

    V8 c = ldg_v8(basep + roff);
    V8 a = ldg_v8(basep + ((long long)yp - y) * N + roff);
    V8 d = ldg_v8(basep + ((long long)ym - y) * N + roff);
    V8 p = ldg_v8(v + bvol + (long long)xp * PLANE + roff);
    V8 m = ldg_v8(v + bvol + (long long)xm * PLANE + roff);

    // ---- gz: straddles via warp shuffle (row == one warp, periodic wrap) ----
    const float left  = __shfl_sync(FULLM, c.f7, (lane + 31) & 31); // z-1
    const float right = __shfl_sync(FULLM, c.f0, (lane + 1)  & 31); // z+8
    V8 gz;
    gz.f0 = (c.f1 - left)  * 0.5f;
    gz.f1 = (c.f2 - c.f0) * 0.5f;
    gz.f2 = (c.f3 - c.f1) * 0.5f;
    gz.f3 = (c.f4 - c.f2) * 0.5f;
    gz.f4 = (c.f5 - c.f3) * 0.5f;
    gz.f5 = (c.f6 - c.f4) * 0.5f;
    gz.f6 = (c.f7 - c.f5) * 0.5f;
    gz.f7 = (right - c.f6) * 0.5f;

    V8 gy = diff_scale(a, d);
    V8 gx = diff_scale(p, m);

    // ---- stores (3 x 256-bit): out[b][comp][x][y][z] ----
    float* __restrict__ ob = out + (long long)b * 3 * VOL
                                 + (long long)x * PLANE + roff;
    stg_v8(ob,             gx);
    stg_v8(ob + VOL,       gy);
    stg_v8(ob + 2LL * VOL, gz);
}

extern "C" void kernel_launch(void* const* d_in, const int* in_sizes, int n_in,
                              void* d_out, int out_size) {
    const float* v = (const float*)d_in[0];
    float* out = (float*)d_out;
    dim3 grid(4 * 256 * 16);
    dim3 block(512);
    fd_grad_kernel<<<grid, block>>>(v, out);
}

// round 13
// speedup vs baseline: 1.0217x; 1.0217x over previous
#include <cuda_runtime.h>

#define N 256
#define NMASK 255
#define PLANE (N * N)            // 65536
#define VOL   (N * N * N)        // 16777216
#define FULLM 0xffffffffu

struct V8 { float f0, f1, f2, f3, f4, f5, f6, f7; };

__device__ __forceinline__ V8 ldg_v8(const float* p) {
    V8 r;
    asm("ld.global.v8.f32 {%0,%1,%2,%3,%4,%5,%6,%7}, [%8];"
        : "=f"(r.f0), "=f"(r.f1), "=f"(r.f2), "=f"(r.f3),
          "=f"(r.f4), "=f"(r.f5), "=f"(r.f6), "=f"(r.f7)
        : "l"(p));
    return r;
}

__device__ __forceinline__ void stg_v8(float* p, const V8& v) {
    asm volatile("st.global.v8.f32 [%0], {%1,%2,%3,%4,%5,%6,%7,%8};"
        :: "l"(p),
           "f"(v.f0), "f"(v.f1), "f"(v.f2), "f"(v.f3),
           "f"(v.f4), "f"(v.f5), "f"(v.f6), "f"(v.f7)
        : "memory");
}

__device__ __forceinline__ V8 diff_scale(const V8& a, const V8& b) {
    V8 r;
    r.f0 = (a.f0 - b.f0) * 0.5f;  r.f1 = (a.f1 - b.f1) * 0.5f;
    r.f2 = (a.f2 - b.f2) * 0.5f;  r.f3 = (a.f3 - b.f3) * 0.5f;
    r.f4 = (a.f4 - b.f4) * 0.5f;  r.f5 = (a.f5 - b.f5) * 0.5f;
    r.f6 = (a.f6 - b.f6) * 0.5f;  r.f7 = (a.f7 - b.f7) * 0.5f;
    return r;
}

// One warp owns one full z-row (32 lanes x 8 floats = 256).
// Block: 256 threads = 8 warps = 8 y-rows.
// Grid: b(4) * x(256) * ygroups(32) = 32768 blocks.
__global__ __launch_bounds__(256)
void fd_grad_kernel(const float* __restrict__ v, float* __restrict__ out) {
    const int t    = threadIdx.x;
    const int w    = t >> 5;            // warp = row slot 0..7
    const int lane = t & 31;

    const unsigned bid = blockIdx.x;
    const int yb = bid & 31;
    const int x  = (bid >> 5) & NMASK;
    const int b  = bid >> 13;

    const int y  = (yb << 3) | w;

    const long long bvol = (long long)b * VOL;
    const float* __restrict__ basep = v + bvol + (long long)x * PLANE;
    const long long roff = (long long)y * N + lane * 8;

    // ---- loads (5 x 256-bit) ----
    const int yp = (y + 1) & NMASK;
    const int ym = (y - 1) & NMASK;
    const int xp = (x + 1) & NMASK;
    const int xm = (x - 1) & NMASK;

    V8 c = ldg_v8(basep + roff);
    V8 a = ldg_v8(basep + ((long long)yp - y) * N + roff);
    V8 d = ldg_v8(basep + ((long long)ym - y) * N + roff);
    V8 p = ldg_v8(v + bvol + (long long)xp * PLANE + roff);
    V8 m = ldg_v8(v + bvol + (long long)xm * PLANE + roff);

    // ---- gz: straddles via warp shuffle (row == one warp, periodic wrap) ----
    const float left  = __shfl_sync(FULLM, c.f7, (lane + 31) & 31); // z-1
    const float right = __shfl_sync(FULLM, c.f0, (lane + 1)  & 31); // z+8
    V8 gz;
    gz.f0 = (c.f1 - left)  * 0.5f;
    gz.f1 = (c.f2 - c.f0) * 0.5f;
    gz.f2 = (c.f3 - c.f1) * 0.5f;
    gz.f3 = (c.f4 - c.f2) * 0.5f;
    gz.f4 = (c.f5 - c.f3) * 0.5f;
    gz.f5 = (c.f6 - c.f4) * 0.5f;
    gz.f6 = (c.f7 - c.f5) * 0.5f;
    gz.f7 = (right - c.f6) * 0.5f;

    V8 gy = diff_scale(a, d);
    V8 gx = diff_scale(p, m);

    // ---- stores (3 x 256-bit): out[b][comp][x][y][z] ----
    float* __restrict__ ob = out + (long long)b * 3 * VOL
                                 + (long long)x * PLANE + roff;
    stg_v8(ob,             gx);
    stg_v8(ob + VOL,       gy);
    stg_v8(ob + 2LL * VOL, gz);
}

extern "C" void kernel_launch(void* const* d_in, const int* in_sizes, int n_in,
                              void* d_out, int out_size) {
    const float* v = (const float*)d_in[0];
    float* out = (float*)d_out;
    dim3 grid(4 * 256 * 32);
    dim3 block(256);
    fd_grad_kernel<<<grid, block>>>(v, out);
}